// round 2
// baseline (speedup 1.0000x reference)
#include <cuda_runtime.h>

#define NUSERS 100000
#define NITEMS 100000
#define NN     200000
#define EMB    64
#define NB     3
#define NE     2000000
#define BATCH  4096
#define REG_W  0.0001f

// ---------------- scratch (static device globals; no runtime alloc) ----------
__device__ float g_total[(size_t)NN * EMB];  // running node embeddings
__device__ float g_x[(size_t)NN * EMB];      // total @ W
__device__ float g_out[(size_t)NN * EMB];    // segment-sum accumulator
__device__ float g_deg[NN];
__device__ float g_dinv[NN];

// ---------------- init: total = concat(user, item); loss = 0 -----------------
__global__ void k_init(const float* __restrict__ ue, const float* __restrict__ ie,
                       float* __restrict__ loss) {
    int i = blockIdx.x * blockDim.x + threadIdx.x;   // exactly NN*EMB threads
    if (i == 0) *loss = 0.f;
    if (i < NUSERS * EMB) g_total[i] = ue[i];
    else                  g_total[i] = ie[i - NUSERS * EMB];
}

// ---------------- reg term: REG_W * 0.5 * (||ue||^2 + ||ie||^2) / BATCH ------
__global__ void k_reg(const float* __restrict__ ue, const float* __restrict__ ie,
                      float* __restrict__ loss) {
    int gid = blockIdx.x * blockDim.x + threadIdx.x;
    int stride = gridDim.x * blockDim.x;
    float s = 0.f;
    for (int i = gid; i < NN * EMB; i += stride) {
        float v = (i < NUSERS * EMB) ? ue[i] : ie[i - NUSERS * EMB];
        s += v * v;
    }
    // block reduce
    for (int o = 16; o; o >>= 1) s += __shfl_xor_sync(0xffffffffu, s, o);
    __shared__ float sm[8];
    int w = threadIdx.x >> 5, l = threadIdx.x & 31;
    if (l == 0) sm[w] = s;
    __syncthreads();
    if (threadIdx.x == 0) {
        float t = 0.f;
        #pragma unroll
        for (int k = 0; k < 8; k++) t += sm[k];
        atomicAdd(loss, t * (REG_W * 0.5f / (float)BATCH));
    }
}

// ---------------- per-behavior: zero out + deg --------------------------------
__global__ void k_prep() {
    int i = blockIdx.x * blockDim.x + threadIdx.x;   // NN*EMB threads
    g_out[i] = 0.f;
    if (i < NN) g_deg[i] = 0.f;
}

// ---------------- degree: deg[col] += 1 ---------------------------------------
__global__ void k_deg(const int* __restrict__ col) {
    int i = blockIdx.x * blockDim.x + threadIdx.x;
    if (i < NE) atomicAdd(&g_deg[col[i]], 1.f);
}

__global__ void k_dinv() {
    int i = blockIdx.x * blockDim.x + threadIdx.x;
    if (i < NN) {
        float d = g_deg[i];
        g_dinv[i] = (d > 0.f) ? rsqrtf(d) : 0.f;
    }
}

// ---------------- GEMM: g_x = g_total @ W  (200000x64 @ 64x64) ----------------
// 64-row tile per block, 256 threads; W + X tile in smem.
__global__ void k_gemm(const float* __restrict__ W) {
    __shared__ float Ws[64 * 64];
    __shared__ float Xs[64 * 65];   // +1 pad to kill bank conflicts on Xs[r][k]
    int t = threadIdx.x;
    size_t rbase = (size_t)blockIdx.x * 64;

    for (int i = t; i < 4096; i += 256) Ws[i] = W[i];
    for (int i = t; i < 4096; i += 256) {
        int r = i >> 6, k = i & 63;
        Xs[r * 65 + k] = g_total[(rbase + r) * 64 + k];
    }
    __syncthreads();

    int r = t >> 3;           // 0..31 (and r+32)
    int c = (t & 7) << 3;     // 0,8,...,56
    float a0[8], a1[8];
    #pragma unroll
    for (int j = 0; j < 8; j++) { a0[j] = 0.f; a1[j] = 0.f; }

    #pragma unroll 8
    for (int k = 0; k < 64; k++) {
        float xa = Xs[r * 65 + k];
        float xb = Xs[(r + 32) * 65 + k];
        #pragma unroll
        for (int j = 0; j < 8; j++) {
            float w = Ws[k * 64 + c + j];
            a0[j] += xa * w;
            a1[j] += xb * w;
        }
    }
    #pragma unroll
    for (int j = 0; j < 8; j++) {
        g_x[(rbase + r) * 64 + c + j]      = a0[j];
        g_x[(rbase + r + 32) * 64 + c + j] = a1[j];
    }
}

// ---------------- scatter: out[col] += dinv[row]*dinv[col] * x[row] -----------
// 16 lanes per edge, each lane moves a float4, vector red (sm_90+).
__global__ void k_scatter(const int* __restrict__ row,
                          const int* __restrict__ col) {
    int g = blockIdx.x * blockDim.x + threadIdx.x;   // NE*16 threads exactly
    int e = g >> 4;
    if (e >= NE) return;
    int l = g & 15;
    int r = row[e];
    int c = col[e];
    float nrm = g_dinv[r] * g_dinv[c];
    if (nrm != 0.f) {
        const float4 v = *reinterpret_cast<const float4*>(&g_x[(size_t)r * 64 + l * 4]);
        float* dst = &g_out[(size_t)c * 64 + l * 4];
        asm volatile("red.global.add.v4.f32 [%0], {%1, %2, %3, %4};"
                     :: "l"(dst), "f"(v.x * nrm), "f"(v.y * nrm),
                        "f"(v.z * nrm), "f"(v.w * nrm)
                     : "memory");
    }
}

// ---------------- normalize + residual: total += l2norm(out + b) --------------
// one warp per node, 2 floats per lane
__global__ void k_norm(const float* __restrict__ b) {
    int node = blockIdx.x * 8 + (threadIdx.x >> 5);
    int l = threadIdx.x & 31;
    if (node >= NN) return;
    size_t base = (size_t)node * 64 + l * 2;
    float2 v = *reinterpret_cast<const float2*>(&g_out[base]);
    v.x += b[l * 2];
    v.y += b[l * 2 + 1];
    float ss = v.x * v.x + v.y * v.y;
    for (int o = 16; o; o >>= 1) ss += __shfl_xor_sync(0xffffffffu, ss, o);
    float inv = 1.f / fmaxf(sqrtf(ss), 1e-12f);
    float2 tt = *reinterpret_cast<const float2*>(&g_total[base]);
    tt.x += v.x * inv;
    tt.y += v.y * inv;
    *reinterpret_cast<float2*>(&g_total[base]) = tt;
}

// ---------------- BPR loss for behavior bi ------------------------------------
// one warp per batch element
__global__ void k_bpr(const int* __restrict__ bd, float* __restrict__ loss,
                      int bi) {
    int b = blockIdx.x * 8 + (threadIdx.x >> 5);
    int l = threadIdx.x & 31;
    if (b >= BATCH) return;
    const int* q = bd + ((size_t)b * NB + bi) * 3;
    int u   = q[0];
    int ip  = q[1];
    int in_ = q[2];
    const float2 uu = *reinterpret_cast<const float2*>(&g_total[(size_t)u * 64 + l * 2]);
    const float2 pp = *reinterpret_cast<const float2*>(&g_total[((size_t)NUSERS + ip) * 64 + l * 2]);
    const float2 nn = *reinterpret_cast<const float2*>(&g_total[((size_t)NUSERS + in_) * 64 + l * 2]);
    float s0 = uu.x * pp.x + uu.y * pp.y;
    float s1 = uu.x * nn.x + uu.y * nn.y;
    for (int o = 16; o; o >>= 1) {
        s0 += __shfl_xor_sync(0xffffffffu, s0, o);
        s1 += __shfl_xor_sync(0xffffffffu, s1, o);
    }
    if (l == 0) {
        float d = s0 - s1;
        float ls = fminf(d, 0.f) - log1pf(expf(-fabsf(d)));   // log_sigmoid(d)
        atomicAdd(loss, -ls / (float)BATCH);
    }
}

// ---------------- launcher -----------------------------------------------------
extern "C" void kernel_launch(void* const* d_in, const int* in_sizes, int n_in,
                              void* d_out, int out_size) {
    const float* ue    = (const float*)d_in[0];
    const float* ie    = (const float*)d_in[1];
    const float* gw    = (const float*)d_in[2];   // [3,64,64]
    const float* gb    = (const float*)d_in[3];   // [3,64]
    const int*   edges = (const int*)d_in[4];     // [3,2,NE] int32 (JAX x64 disabled)
    const int*   bd    = (const int*)d_in[5];     // [BATCH,3,3] int32
    float* loss = (float*)d_out;

    const int NNE = NN * EMB;                 // 12,800,000
    k_init<<<NNE / 256, 256>>>(ue, ie, loss);
    k_reg<<<1024, 256>>>(ue, ie, loss);

    for (int bi = 0; bi < NB; bi++) {
        const int* row = edges + ((size_t)bi * 2 + 0) * NE;
        const int* col = edges + ((size_t)bi * 2 + 1) * NE;

        k_prep<<<NNE / 256, 256>>>();
        k_deg<<<(NE + 255) / 256, 256>>>(col);
        k_dinv<<<(NN + 255) / 256, 256>>>();
        k_gemm<<<NN / 64, 256>>>(gw + (size_t)bi * EMB * EMB);
        k_scatter<<<(NE * 16) / 256, 256>>>(row, col);
        k_norm<<<(NN + 7) / 8, 256>>>(gb + bi * EMB);
        k_bpr<<<(BATCH + 7) / 8, 256>>>(bd, loss, bi);
    }
}

// round 3
// speedup vs baseline: 1.3490x; 1.3490x over previous
#include <cuda_runtime.h>

#define NUSERS 100000
#define NITEMS 100000
#define NN     200000
#define EMB    64
#define NB     3
#define NE     2000000
#define BATCH  4096
#define REG_W  0.0001f
#define NBLK   782              // ceil(NN/256)

// ---------------- scratch (static device globals) ----------------------------
__device__ float g_total[(size_t)NN * EMB];
__device__ float g_x[(size_t)NN * EMB];
__device__ float g_dinv[NN];
__device__ unsigned g_degi[NN];
__device__ int g_off[NN + 1];
__device__ int g_offp[NN];
__device__ int g_bsum[1024];
__device__ int g_bpre[1024];
__device__ int g_cur[NN];
__device__ int g_erow[NE];

// ---------------- init: total = concat(user,item); loss = 0 ------------------
__global__ void k_init(const float* __restrict__ ue, const float* __restrict__ ie,
                       float* __restrict__ loss) {
    int i = blockIdx.x * blockDim.x + threadIdx.x;
    if (i == 0) *loss = 0.f;
    if (i < NUSERS * EMB) g_total[i] = ue[i];
    else                  g_total[i] = ie[i - NUSERS * EMB];
}

// ---------------- reg term ----------------------------------------------------
__global__ void k_reg(const float* __restrict__ ue, const float* __restrict__ ie,
                      float* __restrict__ loss) {
    int gid = blockIdx.x * blockDim.x + threadIdx.x;
    int stride = gridDim.x * blockDim.x;
    float s = 0.f;
    for (int i = gid; i < NN * EMB; i += stride) {
        float v = (i < NUSERS * EMB) ? ue[i] : ie[i - NUSERS * EMB];
        s += v * v;
    }
    for (int o = 16; o; o >>= 1) s += __shfl_xor_sync(0xffffffffu, s, o);
    __shared__ float sm[8];
    int w = threadIdx.x >> 5, l = threadIdx.x & 31;
    if (l == 0) sm[w] = s;
    __syncthreads();
    if (threadIdx.x == 0) {
        float t = 0.f;
        #pragma unroll
        for (int k = 0; k < 8; k++) t += sm[k];
        atomicAdd(loss, t * (REG_W * 0.5f / (float)BATCH));
    }
}

// ---------------- degree histogram --------------------------------------------
__global__ void k_zero() {
    int i = blockIdx.x * blockDim.x + threadIdx.x;
    if (i < NN) g_degi[i] = 0u;
}

__global__ void k_deg(const int* __restrict__ col) {
    int i = blockIdx.x * blockDim.x + threadIdx.x;
    if (i < NE) atomicAdd(&g_degi[col[i]], 1u);
}

// ---------------- 3-phase exclusive scan of degrees ---------------------------
__global__ void k_scan1() {
    __shared__ int sm[256];
    int i = blockIdx.x * 256 + threadIdx.x;
    int v = (i < NN) ? (int)g_degi[i] : 0;
    sm[threadIdx.x] = v;
    __syncthreads();
    for (int o = 1; o < 256; o <<= 1) {
        int t = (threadIdx.x >= o) ? sm[threadIdx.x - o] : 0;
        __syncthreads();
        sm[threadIdx.x] += t;
        __syncthreads();
    }
    if (i < NN) g_offp[i] = sm[threadIdx.x] - v;
    if (threadIdx.x == 255) g_bsum[blockIdx.x] = sm[255];
}

__global__ void k_scan2() {
    __shared__ int sm[1024];
    int t = threadIdx.x;
    int v = (t < NBLK) ? g_bsum[t] : 0;
    sm[t] = v;
    __syncthreads();
    for (int o = 1; o < 1024; o <<= 1) {
        int x = (t >= o) ? sm[t - o] : 0;
        __syncthreads();
        sm[t] += x;
        __syncthreads();
    }
    if (t < NBLK) g_bpre[t] = sm[t] - v;
}

__global__ void k_scan3() {
    int i = blockIdx.x * 256 + threadIdx.x;
    if (i < NN) {
        int o = g_offp[i] + g_bpre[i >> 8];
        g_off[i] = o;
        g_cur[i] = o;
        unsigned d = g_degi[i];
        g_dinv[i] = d ? rsqrtf((float)d) : 0.f;
    }
    if (i == 0) g_off[NN] = NE;
}

// ---------------- bucket edges into CSR ----------------------------------------
__global__ void k_bucket(const int* __restrict__ row, const int* __restrict__ col) {
    int e = blockIdx.x * 256 + threadIdx.x;
    if (e < NE) {
        int c = col[e];
        int p = atomicAdd(&g_cur[c], 1);
        g_erow[p] = row[e];
    }
}

// ---------------- GEMM: g_x = g_total @ W  (200000x64 @ 64x64) -----------------
__global__ void k_gemm(const float* __restrict__ W) {
    __shared__ float Ws[64 * 64];
    __shared__ float Xs[64 * 65];
    int t = threadIdx.x;
    size_t rbase = (size_t)blockIdx.x * 64;

    for (int i = t; i < 4096; i += 256) Ws[i] = W[i];
    for (int i = t; i < 4096; i += 256) {
        int r = i >> 6, k = i & 63;
        Xs[r * 65 + k] = g_total[(rbase + r) * 64 + k];
    }
    __syncthreads();

    int r = t >> 3;
    int c = (t & 7) << 3;
    float a0[8], a1[8];
    #pragma unroll
    for (int j = 0; j < 8; j++) { a0[j] = 0.f; a1[j] = 0.f; }

    #pragma unroll 8
    for (int k = 0; k < 64; k++) {
        float xa = Xs[r * 65 + k];
        float xb = Xs[(r + 32) * 65 + k];
        #pragma unroll
        for (int j = 0; j < 8; j++) {
            float w = Ws[k * 64 + c + j];
            a0[j] += xa * w;
            a1[j] += xb * w;
        }
    }
    #pragma unroll
    for (int j = 0; j < 8; j++) {
        g_x[(rbase + r) * 64 + c + j]      = a0[j];
        g_x[(rbase + r + 32) * 64 + c + j] = a1[j];
    }
}

// ---------------- fused gather segment-sum + bias + l2norm + residual ----------
// one warp per node, float2 per lane
__global__ void k_gather_norm(const float* __restrict__ b) {
    int node = blockIdx.x * 8 + (threadIdx.x >> 5);
    int l = threadIdx.x & 31;
    if (node >= NN) return;
    int s = g_off[node], e = g_off[node + 1];
    float dc = g_dinv[node];
    float ax = 0.f, ay = 0.f;
    for (int j = s; j < e; j++) {
        int r = __ldg(&g_erow[j]);
        float nrm = dc * g_dinv[r];
        float2 v = *reinterpret_cast<const float2*>(&g_x[(size_t)r * 64 + l * 2]);
        ax += nrm * v.x;
        ay += nrm * v.y;
    }
    ax += b[l * 2];
    ay += b[l * 2 + 1];
    float ss = ax * ax + ay * ay;
    for (int o = 16; o; o >>= 1) ss += __shfl_xor_sync(0xffffffffu, ss, o);
    float inv = 1.f / fmaxf(sqrtf(ss), 1e-12f);
    size_t base = (size_t)node * 64 + l * 2;
    float2 tt = *reinterpret_cast<const float2*>(&g_total[base]);
    tt.x += ax * inv;
    tt.y += ay * inv;
    *reinterpret_cast<float2*>(&g_total[base]) = tt;
}

// ---------------- BPR loss ------------------------------------------------------
__global__ void k_bpr(const int* __restrict__ bd, float* __restrict__ loss, int bi) {
    int b = blockIdx.x * 8 + (threadIdx.x >> 5);
    int l = threadIdx.x & 31;
    if (b >= BATCH) return;
    const int* q = bd + ((size_t)b * NB + bi) * 3;
    int u = q[0], ip = q[1], in_ = q[2];
    const float2 uu = *reinterpret_cast<const float2*>(&g_total[(size_t)u * 64 + l * 2]);
    const float2 pp = *reinterpret_cast<const float2*>(&g_total[((size_t)NUSERS + ip) * 64 + l * 2]);
    const float2 nn = *reinterpret_cast<const float2*>(&g_total[((size_t)NUSERS + in_) * 64 + l * 2]);
    float s0 = uu.x * pp.x + uu.y * pp.y;
    float s1 = uu.x * nn.x + uu.y * nn.y;
    for (int o = 16; o; o >>= 1) {
        s0 += __shfl_xor_sync(0xffffffffu, s0, o);
        s1 += __shfl_xor_sync(0xffffffffu, s1, o);
    }
    if (l == 0) {
        float d = s0 - s1;
        float ls = fminf(d, 0.f) - log1pf(expf(-fabsf(d)));
        atomicAdd(loss, -ls / (float)BATCH);
    }
}

// ---------------- launcher ------------------------------------------------------
extern "C" void kernel_launch(void* const* d_in, const int* in_sizes, int n_in,
                              void* d_out, int out_size) {
    const float* ue    = (const float*)d_in[0];
    const float* ie    = (const float*)d_in[1];
    const float* gw    = (const float*)d_in[2];   // [3,64,64]
    const float* gb    = (const float*)d_in[3];   // [3,64]
    const int*   edges = (const int*)d_in[4];     // [3,2,NE] int32
    const int*   bd    = (const int*)d_in[5];     // [BATCH,3,3] int32
    float* loss = (float*)d_out;

    const int NNE = NN * EMB;
    k_init<<<NNE / 256, 256>>>(ue, ie, loss);
    k_reg<<<1024, 256>>>(ue, ie, loss);

    for (int bi = 0; bi < NB; bi++) {
        const int* row = edges + ((size_t)bi * 2 + 0) * NE;
        const int* col = edges + ((size_t)bi * 2 + 1) * NE;

        k_zero<<<(NN + 255) / 256, 256>>>();
        k_deg<<<(NE + 255) / 256, 256>>>(col);
        k_scan1<<<NBLK, 256>>>();
        k_scan2<<<1, 1024>>>();
        k_scan3<<<NBLK, 256>>>();
        k_gemm<<<NN / 64, 256>>>(gw + (size_t)bi * EMB * EMB);
        k_bucket<<<(NE + 255) / 256, 256>>>(row, col);
        k_gather_norm<<<(NN + 7) / 8, 256>>>(gb + bi * EMB);
        k_bpr<<<(BATCH + 7) / 8, 256>>>(bd, loss, bi);
    }
}

// round 4
// speedup vs baseline: 1.6934x; 1.2553x over previous
#include <cuda_runtime.h>

#define NUSERS 100000
#define NITEMS 100000
#define NN     200000
#define EMB    64
#define NB     3
#define NE     2000000
#define BATCH  4096
#define REG_W  0.0001f

#define NN3    (NB * NN)          // 600000
#define NE3    (NB * NE)          // 6000000
#define SCB    1024
#define NBLK1  ((NN3 + SCB - 1) / SCB)   // 586

// ---------------- scratch (static device globals) ----------------------------
__device__ float g_t0[(size_t)NN * EMB];
__device__ float g_t1[(size_t)NN * EMB];
__device__ float g_dinv[NN3];
__device__ unsigned g_degi[NN3];
__device__ int g_off[NN3 + 1];
__device__ int g_cur[NN3];
__device__ int g_bsum[SCB];
__device__ int g_bpre[SCB];
__device__ int g_erow[NE3];

// ---------------- init: t0 = concat(user,item); loss = 0 ----------------------
__global__ void k_init(const float* __restrict__ ue, const float* __restrict__ ie,
                       float* __restrict__ loss) {
    int i = blockIdx.x * blockDim.x + threadIdx.x;
    if (i == 0) *loss = 0.f;
    if (i < NUSERS * EMB) g_t0[i] = ue[i];
    else                  g_t0[i] = ie[i - NUSERS * EMB];
}

// ---------------- reg term ----------------------------------------------------
__global__ void k_reg(const float* __restrict__ ue, const float* __restrict__ ie,
                      float* __restrict__ loss) {
    int gid = blockIdx.x * blockDim.x + threadIdx.x;
    int stride = gridDim.x * blockDim.x;
    float s = 0.f;
    for (int i = gid; i < NN * EMB; i += stride) {
        float v = (i < NUSERS * EMB) ? ue[i] : ie[i - NUSERS * EMB];
        s += v * v;
    }
    for (int o = 16; o; o >>= 1) s += __shfl_xor_sync(0xffffffffu, s, o);
    __shared__ float sm[8];
    int w = threadIdx.x >> 5, l = threadIdx.x & 31;
    if (l == 0) sm[w] = s;
    __syncthreads();
    if (threadIdx.x == 0) {
        float t = 0.f;
        #pragma unroll
        for (int k = 0; k < 8; k++) t += sm[k];
        atomicAdd(loss, t * (REG_W * 0.5f / (float)BATCH));
    }
}

// ---------------- degree histogram, all behaviors -----------------------------
__global__ void k_zero3() {
    int i = blockIdx.x * blockDim.x + threadIdx.x;
    if (i < NN3) g_degi[i] = 0u;
}

__global__ void k_deg3(const int* __restrict__ edges) {
    int i = blockIdx.x * blockDim.x + threadIdx.x;
    if (i < NE3) {
        int b = i / NE, e = i - b * NE;
        int c = edges[((size_t)b * 2 + 1) * NE + e];
        atomicAdd(&g_degi[b * NN + c], 1u);
    }
}

// ---------------- 3-phase exclusive scan over 600k degrees --------------------
__global__ void k_scan1() {
    __shared__ int sm[SCB];
    int i = blockIdx.x * SCB + threadIdx.x;
    int v = (i < NN3) ? (int)g_degi[i] : 0;
    sm[threadIdx.x] = v;
    __syncthreads();
    for (int o = 1; o < SCB; o <<= 1) {
        int t = (threadIdx.x >= o) ? sm[threadIdx.x - o] : 0;
        __syncthreads();
        sm[threadIdx.x] += t;
        __syncthreads();
    }
    if (i < NN3) g_off[i] = sm[threadIdx.x] - v;   // partial exclusive
    if (threadIdx.x == SCB - 1) g_bsum[blockIdx.x] = sm[SCB - 1];
}

__global__ void k_scan2() {
    __shared__ int sm[SCB];
    int t = threadIdx.x;
    int v = (t < NBLK1) ? g_bsum[t] : 0;
    sm[t] = v;
    __syncthreads();
    for (int o = 1; o < SCB; o <<= 1) {
        int x = (t >= o) ? sm[t - o] : 0;
        __syncthreads();
        sm[t] += x;
        __syncthreads();
    }
    if (t < NBLK1) g_bpre[t] = sm[t] - v;
}

__global__ void k_scan3() {
    int i = blockIdx.x * SCB + threadIdx.x;
    if (i < NN3) {
        int o = g_off[i] + g_bpre[i / SCB];
        g_off[i] = o;
        g_cur[i] = o;
        unsigned d = g_degi[i];
        g_dinv[i] = d ? rsqrtf((float)d) : 0.f;
    }
    if (i == 0) g_off[NN3] = NE3;
}

// ---------------- bucket all edges into CSR ------------------------------------
__global__ void k_bucket3(const int* __restrict__ edges) {
    int i = blockIdx.x * blockDim.x + threadIdx.x;
    if (i < NE3) {
        int b = i / NE, e = i - b * NE;
        int r = edges[((size_t)b * 2 + 0) * NE + e];
        int c = edges[((size_t)b * 2 + 1) * NE + e];
        int p = atomicAdd(&g_cur[b * NN + c], 1);
        g_erow[p] = r;
    }
}

// ---------------- fused: gather-sum + matvec(W) + bias + l2norm + residual -----
// one warp per node (grid-stride); reads tA, writes tB (ping-pong, race-free)
__global__ void k_gather(const float* __restrict__ tA, float* __restrict__ tB,
                         const float* __restrict__ W, const float* __restrict__ bias,
                         int bi) {
    __shared__ float Wt[64 * 65];     // transposed, padded: Wt[j*65+k] = W[k][j]
    __shared__ float sbuf[8][64];
    __shared__ float bsh[64];
    int t = threadIdx.x;
    for (int i = t; i < 4096; i += 256) {
        int k = i >> 6, j = i & 63;
        Wt[j * 65 + k] = W[i];
    }
    if (t < 64) bsh[t] = bias[t];
    __syncthreads();

    int w = t >> 5, l = t & 31;
    const float* dinv = g_dinv + bi * NN;
    const int*   off  = g_off  + bi * NN;

    for (int node = blockIdx.x * 8 + w; node < NN; node += gridDim.x * 8) {
        int s0 = off[node], e0 = off[node + 1];
        float ax = 0.f, ay = 0.f;
        #pragma unroll 2
        for (int j = s0; j < e0; j++) {
            int r = __ldg(&g_erow[j]);
            float dr = __ldg(&dinv[r]);
            float2 v = *reinterpret_cast<const float2*>(&tA[(size_t)r * 64 + l * 2]);
            ax += dr * v.x;
            ay += dr * v.y;
        }
        float dn = dinv[node];
        sbuf[w][2 * l]     = ax * dn;
        sbuf[w][2 * l + 1] = ay * dn;
        __syncwarp();

        // y = s @ W + b ; lane l computes outputs l and l+32 (conflict-free)
        float y0 = bsh[l], y1 = bsh[l + 32];
        #pragma unroll 16
        for (int k = 0; k < 64; k++) {
            float sk = sbuf[w][k];
            y0 += sk * Wt[l * 65 + k];
            y1 += sk * Wt[(l + 32) * 65 + k];
        }
        float ss = y0 * y0 + y1 * y1;
        for (int o = 16; o; o >>= 1) ss += __shfl_xor_sync(0xffffffffu, ss, o);
        float inv = 1.f / fmaxf(sqrtf(ss), 1e-12f);

        size_t base = (size_t)node * 64;
        tB[base + l]      = tA[base + l]      + y0 * inv;
        tB[base + l + 32] = tA[base + l + 32] + y1 * inv;
        __syncwarp();
    }
}

// ---------------- BPR loss ------------------------------------------------------
__global__ void k_bpr(const float* __restrict__ tot, const int* __restrict__ bd,
                      float* __restrict__ loss, int bi) {
    int b = blockIdx.x * 8 + (threadIdx.x >> 5);
    int l = threadIdx.x & 31;
    if (b >= BATCH) return;
    const int* q = bd + ((size_t)b * NB + bi) * 3;
    int u = q[0], ip = q[1], in_ = q[2];
    const float2 uu = *reinterpret_cast<const float2*>(&tot[(size_t)u * 64 + l * 2]);
    const float2 pp = *reinterpret_cast<const float2*>(&tot[((size_t)NUSERS + ip) * 64 + l * 2]);
    const float2 nn = *reinterpret_cast<const float2*>(&tot[((size_t)NUSERS + in_) * 64 + l * 2]);
    float s0 = uu.x * pp.x + uu.y * pp.y;
    float s1 = uu.x * nn.x + uu.y * nn.y;
    for (int o = 16; o; o >>= 1) {
        s0 += __shfl_xor_sync(0xffffffffu, s0, o);
        s1 += __shfl_xor_sync(0xffffffffu, s1, o);
    }
    if (l == 0) {
        float d = s0 - s1;
        float ls = fminf(d, 0.f) - log1pf(expf(-fabsf(d)));
        atomicAdd(loss, -ls / (float)BATCH);
    }
}

// ---------------- launcher ------------------------------------------------------
extern "C" void kernel_launch(void* const* d_in, const int* in_sizes, int n_in,
                              void* d_out, int out_size) {
    const float* ue    = (const float*)d_in[0];
    const float* ie    = (const float*)d_in[1];
    const float* gw    = (const float*)d_in[2];   // [3,64,64]
    const float* gb    = (const float*)d_in[3];   // [3,64]
    const int*   edges = (const int*)d_in[4];     // [3,2,NE] int32
    const int*   bd    = (const int*)d_in[5];     // [BATCH,3,3] int32
    float* loss = (float*)d_out;

    const int NNE = NN * EMB;
    k_init<<<NNE / 256, 256>>>(ue, ie, loss);
    k_reg<<<1024, 256>>>(ue, ie, loss);

    // one-shot CSR build for all behaviors
    k_zero3<<<(NN3 + 255) / 256, 256>>>();
    k_deg3<<<(NE3 + 255) / 256, 256>>>(edges);
    k_scan1<<<NBLK1, SCB>>>();
    k_scan2<<<1, SCB>>>();
    k_scan3<<<NBLK1, SCB>>>();
    k_bucket3<<<(NE3 + 255) / 256, 256>>>(edges);

    // ping-pong buffers
    float* bufs[2] = { (float*)0, (float*)0 };
    cudaGetSymbolAddress((void**)&bufs[0], g_t0);
    cudaGetSymbolAddress((void**)&bufs[1], g_t1);

    for (int bi = 0; bi < NB; bi++) {
        const float* tA = bufs[bi & 1];
        float*       tB = bufs[(bi + 1) & 1];
        k_gather<<<1184, 256>>>(tA, tB, gw + (size_t)bi * EMB * EMB, gb + bi * EMB, bi);
        k_bpr<<<(BATCH + 7) / 8, 256>>>(tB, bd, loss, bi);
    }
}